// round 1
// baseline (speedup 1.0000x reference)
#include <cuda_runtime.h>
#include <cstddef>

#define B_    4
#define N_    8192
#define K_    32
#define C_    64
#define CIN_  67
#define CINP_ 68   // padded row (17 float4)

// transposed features: fT[b][n][c] (contiguous 256B per point)
__device__ float g_fT[(size_t)B_ * N_ * C_];

// ---------------------------------------------------------------------------
// f [B][C][N] -> g_fT [B][N][C]
// ---------------------------------------------------------------------------
__global__ void transpose_f_kernel(const float* __restrict__ f) {
    __shared__ float tile[32][33];
    const int b  = blockIdx.z;
    const int c0 = blockIdx.y * 32;
    const int n0 = blockIdx.x * 32;
    const int tx = threadIdx.x, ty = threadIdx.y;   // 32 x 8
#pragma unroll
    for (int i = 0; i < 32; i += 8)
        tile[ty + i][tx] = f[((size_t)b * C_ + (c0 + ty + i)) * N_ + n0 + tx];
    __syncthreads();
#pragma unroll
    for (int i = 0; i < 32; i += 8)
        g_fT[((size_t)b * N_ + (n0 + ty + i)) * C_ + c0 + tx] = tile[tx][ty + i];
}

// ---------------------------------------------------------------------------
// Main kernel: one warp per point (lane = neighbor k), 8 warps/block,
// block handles 32 consecutive points of one batch (4 points per warp).
// ---------------------------------------------------------------------------
__global__ void __launch_bounds__(256, 1)
lpamlp_kernel(const float* __restrict__ p, const int* __restrict__ idx,
              const float* __restrict__ W_attn, const float* __restrict__ b_attn,
              const float* __restrict__ W1, const float* __restrict__ b1,
              const float* __restrict__ W2, const float* __restrict__ b2,
              const float* __restrict__ Wf1, const float* __restrict__ bf1,
              const float* __restrict__ Wf2, const float* __restrict__ bf2,
              float* __restrict__ out_f2)
{
    extern __shared__ float sm[];
    float* Ws    = sm;                      // 128 * 68  (rows 0..63: W_attn, 64..127: W1), zero-padded col 67
    float* W2s   = Ws + 128 * CINP_;        // 64*64
    float* Wf1T  = W2s + 4096;              // [i][o]
    float* Wf2T  = Wf1T + 4096;             // [i][o]
    float* bs    = Wf2T + 4096;             // 5*64: b_attn, b1, b2, bf1, bf2
    float* fo_sh = bs + 320;                // 8*68
    float* g1_sh = fo_sh + 8 * CINP_;       // 8*68
    float* fres  = g1_sh + 8 * CINP_;       // 8*68
    float* tile  = fres + 8 * CINP_;        // 64*33 output staging

    const int tid  = threadIdx.x;
    const int b    = blockIdx.y;
    const int n0   = blockIdx.x * 32;
    const int warp = tid >> 5, lane = tid & 31;

    // ---- stage weights/biases into shared ----
    for (int i = tid; i < 128 * CINP_; i += 256) {
        int r = i / CINP_, c = i - r * CINP_;
        float v = 0.f;
        if (c < CIN_) v = (r < 64) ? W_attn[r * CIN_ + c] : W1[(r - 64) * CIN_ + c];
        Ws[i] = v;
    }
    for (int i = tid; i < 4096; i += 256) {
        W2s[i] = W2[i];
        int r = i >> 6, c = i & 63;          // global layout [o][i]: r=o, c=i
        Wf1T[c * 64 + r] = Wf1[i];
        Wf2T[c * 64 + r] = Wf2[i];
    }
    if (tid < 64) {
        bs[tid]       = b_attn[tid];
        bs[64 + tid]  = b1[tid];
        bs[128 + tid] = b2[tid];
        bs[192 + tid] = bf1[tid];
        bs[256 + tid] = bf2[tid];
    }
    __syncthreads();

    for (int j = 0; j < 4; j++) {
        const int nl = warp * 4 + j;         // 0..31 within tile
        const int n  = n0 + nl;
        const int nb = idx[((size_t)(b * N_ + n)) * K_ + lane];

        // ---- gather x = [dp(3); fj(64)] into registers ----
        float x[CINP_];
        {
            const float* pj = p + ((size_t)b * N_ + nb) * 3;
            const float* pc = p + ((size_t)b * N_ + n) * 3;
            x[0] = pj[0] - pc[0];
            x[1] = pj[1] - pc[1];
            x[2] = pj[2] - pc[2];
            const float4* fj = (const float4*)(g_fT + ((size_t)b * N_ + nb) * C_);
#pragma unroll
            for (int q = 0; q < 16; q++) {
                float4 v = fj[q];
                x[3 + 4 * q] = v.x; x[4 + 4 * q] = v.y;
                x[5 + 4 * q] = v.z; x[6 + 4 * q] = v.w;
            }
            x[67] = 0.f;
            // residual features for this point
            const float* frow = g_fT + ((size_t)b * N_ + n) * C_;
            fres[warp * CINP_ + lane]      = frow[lane];
            fres[warp * CINP_ + 32 + lane] = frow[32 + lane];
        }
        __syncwarp();

        // ---- pass A: h[c] = relu(W1 @ x + b1), h kept in registers ----
        float h[64];
#pragma unroll
        for (int c = 0; c < 64; c++) {
            float a0 = bs[64 + c], a1 = 0.f, a2 = 0.f, a3 = 0.f;
            const float4* wr = (const float4*)(Ws + (64 + c) * CINP_);
#pragma unroll
            for (int q = 0; q < 17; q++) {
                float4 w = wr[q];
                a0 += w.x * x[4 * q + 0];
                a1 += w.y * x[4 * q + 1];
                a2 += w.z * x[4 * q + 2];
                a3 += w.w * x[4 * q + 3];
            }
            h[c] = fmaxf((a0 + a1) + (a2 + a3), 0.f);
        }

        // ---- pass B: per channel pair -> attn, xi, softmax over lanes, fo ----
#pragma unroll 1
        for (int cp = 0; cp < 32; cp++) {
            const int c0 = cp * 2, c1 = cp * 2 + 1;

            float a00 = bs[c0], a01 = 0.f, a02 = 0.f, a03 = 0.f;
            float a10 = bs[c1], a11 = 0.f, a12 = 0.f, a13 = 0.f;
            const float4* w0 = (const float4*)(Ws + c0 * CINP_);
            const float4* w1 = (const float4*)(Ws + c1 * CINP_);
#pragma unroll
            for (int q = 0; q < 17; q++) {
                float4 u = w0[q], v = w1[q];
                a00 += u.x * x[4 * q + 0];  a10 += v.x * x[4 * q + 0];
                a01 += u.y * x[4 * q + 1];  a11 += v.y * x[4 * q + 1];
                a02 += u.z * x[4 * q + 2];  a12 += v.z * x[4 * q + 2];
                a03 += u.w * x[4 * q + 3];  a13 += v.w * x[4 * q + 3];
            }
            const float at0 = (a00 + a01) + (a02 + a03);
            const float at1 = (a10 + a11) + (a12 + a13);

            float q00 = bs[128 + c0], q01 = 0.f, q02 = 0.f, q03 = 0.f;
            float q10 = bs[128 + c1], q11 = 0.f, q12 = 0.f, q13 = 0.f;
            const float4* v0 = (const float4*)(W2s + c0 * 64);
            const float4* v1 = (const float4*)(W2s + c1 * 64);
#pragma unroll
            for (int q = 0; q < 16; q++) {
                float4 u = v0[q], v = v1[q];
                q00 += u.x * h[4 * q + 0];  q10 += v.x * h[4 * q + 0];
                q01 += u.y * h[4 * q + 1];  q11 += v.y * h[4 * q + 1];
                q02 += u.z * h[4 * q + 2];  q12 += v.z * h[4 * q + 2];
                q03 += u.w * h[4 * q + 3];  q13 += v.w * h[4 * q + 3];
            }
            const float xi0 = (q00 + q01) + (q02 + q03);
            const float xi1 = (q10 + q11) + (q12 + q13);

            // softmax over the 32 lanes (neighbors), two channels interleaved
            float m0 = at0, m1 = at1;
#pragma unroll
            for (int o = 16; o > 0; o >>= 1) {
                m0 = fmaxf(m0, __shfl_xor_sync(0xffffffffu, m0, o));
                m1 = fmaxf(m1, __shfl_xor_sync(0xffffffffu, m1, o));
            }
            const float e0 = __expf(at0 - m0);
            const float e1 = __expf(at1 - m1);
            float s0 = e0, t0 = e0 * xi0;
            float s1 = e1, t1 = e1 * xi1;
#pragma unroll
            for (int o = 16; o > 0; o >>= 1) {
                s0 += __shfl_xor_sync(0xffffffffu, s0, o);
                t0 += __shfl_xor_sync(0xffffffffu, t0, o);
                s1 += __shfl_xor_sync(0xffffffffu, s1, o);
                t1 += __shfl_xor_sync(0xffffffffu, t1, o);
            }
            if (lane == 0) {
                float fo0 = fmaxf(__fdividef(t0, s0) + fres[warp * CINP_ + c0], 0.f);
                float fo1 = fmaxf(__fdividef(t1, s1) + fres[warp * CINP_ + c1], 0.f);
                fo_sh[warp * CINP_ + c0] = fo0;
                fo_sh[warp * CINP_ + c1] = fo1;
            }
        }
        __syncwarp();

        // ---- epilogue: FFN (each lane owns channels 2*lane, 2*lane+1) ----
        {
            const int ca = 2 * lane, cb = 2 * lane + 1;
            float g1a = bs[192 + ca], g1b = bs[192 + cb];
#pragma unroll
            for (int i = 0; i < 64; i++) {
                float  fv = fo_sh[warp * CINP_ + i];
                float2 w  = ((const float2*)(Wf1T + i * 64))[lane];
                g1a += w.x * fv;
                g1b += w.y * fv;
            }
            g1a = fmaxf(g1a, 0.f);
            g1b = fmaxf(g1b, 0.f);
            ((float2*)(g1_sh + warp * CINP_))[lane] = make_float2(g1a, g1b);
            __syncwarp();

            float g2a = bs[256 + ca], g2b = bs[256 + cb];
#pragma unroll
            for (int i = 0; i < 64; i++) {
                float  gv = g1_sh[warp * CINP_ + i];
                float2 w  = ((const float2*)(Wf2T + i * 64))[lane];
                g2a += w.x * gv;
                g2b += w.y * gv;
            }
            const float f2a = fmaxf(g2a + fo_sh[warp * CINP_ + ca], 0.f);
            const float f2b = fmaxf(g2b + fo_sh[warp * CINP_ + cb], 0.f);
            tile[ca * 33 + nl] = f2a;
            tile[cb * 33 + nl] = f2b;
        }
        __syncwarp();
    }

    // ---- coalesced write of the 32-point tile: f2 [B][C][N] ----
    __syncthreads();
#pragma unroll
    for (int r = warp; r < 64; r += 8)
        out_f2[((size_t)b * 64 + r) * N_ + n0 + lane] = tile[r * 33 + lane];
}

// ---------------------------------------------------------------------------
// launch
// ---------------------------------------------------------------------------
static const int SMEM_FLOATS =
    128 * CINP_ + 3 * 4096 + 320 + 3 * 8 * CINP_ + 64 * 33;
static const int SMEM_BYTES = SMEM_FLOATS * 4;

extern "C" void kernel_launch(void* const* d_in, const int* in_sizes, int n_in,
                              void* d_out, int out_size)
{
    const float* p      = (const float*)d_in[0];
    const float* f      = (const float*)d_in[1];
    const int*   idx    = (const int*)d_in[2];
    const float* W_attn = (const float*)d_in[3];
    const float* b_attn = (const float*)d_in[4];
    const float* W1     = (const float*)d_in[5];
    const float* b1     = (const float*)d_in[6];
    const float* W2     = (const float*)d_in[7];
    const float* b2     = (const float*)d_in[8];
    const float* Wf1    = (const float*)d_in[9];
    const float* bf1    = (const float*)d_in[10];
    const float* Wf2    = (const float*)d_in[11];
    const float* bf2    = (const float*)d_in[12];

    float* out = (float*)d_out;
    const int psz = B_ * N_ * 3;
    const int fsz = B_ * C_ * N_;

    float* out_f2 = out;
    if (out_size >= psz + fsz) {
        // tuple output: p first, then f2
        cudaMemcpyAsync(out, p, (size_t)psz * sizeof(float),
                        cudaMemcpyDeviceToDevice);
        out_f2 = out + psz;
    }

    transpose_f_kernel<<<dim3(N_ / 32, C_ / 32, B_), dim3(32, 8)>>>(f);

    cudaFuncSetAttribute(lpamlp_kernel,
                         cudaFuncAttributeMaxDynamicSharedMemorySize,
                         SMEM_BYTES);
    lpamlp_kernel<<<dim3(N_ / 32, B_), 256, SMEM_BYTES>>>(
        p, idx, W_attn, b_attn, W1, b1, W2, b2, Wf1, bf1, Wf2, bf2, out_f2);
}

// round 2
// speedup vs baseline: 1.1372x; 1.1372x over previous
#include <cuda_runtime.h>
#include <cstddef>

#define B_    4
#define N_    8192
#define K_    32
#define C_    64
#define CIN_  67
#define CINP_ 68   // padded input row: [dx,dy,dz,0,f0..f63] -> 17 x 16B

// ---------------------------------------------------------------------------
// constant weights: rows 0..63 W_attn (padded 68), rows 64..127 W1 (padded 68),
// then W2 [64][64] at 8704, then biases b_attn/b1/b2 at 12800/12864/12928.
// ---------------------------------------------------------------------------
#define CW_FLOATS 12992
__constant__ float cW[CW_FLOATS];
__device__ float g_stage[CW_FLOATS];

// transposed features: fT[b][n][c] (contiguous 256B per point)
__device__ float g_fT[(size_t)B_ * N_ * C_];

// ---------------------------------------------------------------------------
// f32x2 helpers
// ---------------------------------------------------------------------------
typedef unsigned long long u64;

__device__ __forceinline__ void fma2(u64& d, u64 a, u64 b) {
    asm("fma.rn.f32x2 %0, %1, %2, %0;" : "+l"(d) : "l"(a), "l"(b));
}
__device__ __forceinline__ u64 add2(u64 a, u64 b) {
    u64 r; asm("add.rn.f32x2 %0, %1, %2;" : "=l"(r) : "l"(a), "l"(b)); return r;
}
__device__ __forceinline__ u64 pk2(float lo, float hi) {
    u64 r; asm("mov.b64 %0, {%1, %2};" : "=l"(r) : "f"(lo), "f"(hi)); return r;
}
__device__ __forceinline__ float red2(u64 a, u64 b) {
    u64 s = add2(a, b);
    float lo, hi;
    asm("mov.b64 {%0, %1}, %2;" : "=f"(lo), "=f"(hi) : "l"(s));
    return lo + hi;
}

// ---------------------------------------------------------------------------
// stage + reorder weights into g_stage (then memcpy'd into cW)
// ---------------------------------------------------------------------------
__global__ void stage_weights_kernel(const float* __restrict__ W_attn,
                                     const float* __restrict__ W1,
                                     const float* __restrict__ W2,
                                     const float* __restrict__ b_attn,
                                     const float* __restrict__ b1,
                                     const float* __restrict__ b2) {
    const int t = blockIdx.x * blockDim.x + threadIdx.x;
    const int nt = gridDim.x * blockDim.x;
    for (int i = t; i < 128 * CINP_; i += nt) {
        int r = i / CINP_, c = i - r * CINP_;
        const float* src = (r < 64) ? (W_attn + r * CIN_) : (W1 + (r - 64) * CIN_);
        float v = (c < 3) ? src[c] : (c == 3 ? 0.f : src[c - 1]);
        g_stage[i] = v;
    }
    for (int i = t; i < 4096; i += nt) g_stage[8704 + i] = W2[i];
    for (int i = t; i < 64; i += nt) {
        g_stage[12800 + i] = b_attn[i];
        g_stage[12864 + i] = b1[i];
        g_stage[12928 + i] = b2[i];
    }
}

// ---------------------------------------------------------------------------
// f [B][C][N] -> g_fT [B][N][C]
// ---------------------------------------------------------------------------
__global__ void transpose_f_kernel(const float* __restrict__ f) {
    __shared__ float tile[32][33];
    const int b  = blockIdx.z;
    const int c0 = blockIdx.y * 32;
    const int n0 = blockIdx.x * 32;
    const int tx = threadIdx.x, ty = threadIdx.y;   // 32 x 8
#pragma unroll
    for (int i = 0; i < 32; i += 8)
        tile[ty + i][tx] = f[((size_t)b * C_ + (c0 + ty + i)) * N_ + n0 + tx];
    __syncthreads();
#pragma unroll
    for (int i = 0; i < 32; i += 8)
        g_fT[((size_t)b * N_ + (n0 + ty + i)) * C_ + c0 + tx] = tile[tx][ty + i];
}

// ---------------------------------------------------------------------------
// Main kernel: one warp per point (lane = neighbor k), 8 warps/block,
// block handles 32 consecutive points of one batch (4 points per warp).
// Weights on the uniform-const port, math in packed f32x2.
// ---------------------------------------------------------------------------
__global__ void __launch_bounds__(256, 1)
lpamlp_kernel(const float* __restrict__ p, const int* __restrict__ idx,
              const float* __restrict__ Wf1, const float* __restrict__ bf1,
              const float* __restrict__ Wf2, const float* __restrict__ bf2,
              float* __restrict__ out_f2)
{
    __shared__ float Wf1T[4096];          // [i][o]
    __shared__ float Wf2T[4096];          // [i][o]
    __shared__ float bsf[128];            // bf1, bf2
    __shared__ float fo_sh[8 * CINP_];
    __shared__ float g1_sh[8 * CINP_];
    __shared__ float fres[8 * CINP_];
    __shared__ float tile[64 * 33];       // output staging

    const int tid  = threadIdx.x;
    const int b    = blockIdx.y;
    const int n0   = blockIdx.x * 32;
    const int warp = tid >> 5, lane = tid & 31;

    for (int i = tid; i < 4096; i += 256) {
        int r = i >> 6, c = i & 63;       // global layout [o][i]
        Wf1T[c * 64 + r] = Wf1[i];
        Wf2T[c * 64 + r] = Wf2[i];
    }
    if (tid < 64) {
        bsf[tid]      = bf1[tid];
        bsf[64 + tid] = bf2[tid];
    }
    __syncthreads();

#pragma unroll 1
    for (int j = 0; j < 4; j++) {
        const int nl = warp * 4 + j;
        const int n  = n0 + nl;
        const int nb = idx[((size_t)(b * N_ + n)) * K_ + lane];

        // ---- gather x2 = [(dx,dy),(dz,0),(f pairs)...] packed f32x2 ----
        u64 x2[34];
        {
            const float* pj = p + ((size_t)b * N_ + nb) * 3;
            const float* pc = p + ((size_t)b * N_ + n) * 3;
            x2[0] = pk2(pj[0] - pc[0], pj[1] - pc[1]);
            x2[1] = pk2(pj[2] - pc[2], 0.f);
            const ulonglong2* fj =
                (const ulonglong2*)(g_fT + ((size_t)b * N_ + nb) * C_);
#pragma unroll
            for (int q = 0; q < 16; q++) {
                ulonglong2 v = fj[q];
                x2[2 + 2 * q] = v.x;
                x2[3 + 2 * q] = v.y;
            }
            const float* frow = g_fT + ((size_t)b * N_ + n) * C_;
            fres[warp * CINP_ + lane]      = frow[lane];
            fres[warp * CINP_ + 32 + lane] = frow[32 + lane];
        }
        __syncwarp();

        // ---- pass A: h = relu(W1 @ x + b1), packed pairs h2[m]=(h[2m],h[2m+1]) ----
        u64 h2[32];
#pragma unroll
        for (int t = 0; t < 32; t++) {
            const int c0 = 2 * t;
            const ulonglong2* w0 =
                (const ulonglong2*)(cW + (64 + c0) * CINP_);
            u64 a0 = 0, a1 = 0, b0 = 0, b1v = 0;
#pragma unroll
            for (int q = 0; q < 17; q++) {
                ulonglong2 u = w0[q];
                ulonglong2 v = w0[q + 17];
                fma2(a0, u.x, x2[2 * q]);
                fma2(a1, u.y, x2[2 * q + 1]);
                fma2(b0, v.x, x2[2 * q]);
                fma2(b1v, v.y, x2[2 * q + 1]);
            }
            float h0 = fmaxf(red2(a0, a1) + cW[12864 + c0], 0.f);
            float h1 = fmaxf(red2(b0, b1v) + cW[12865 + c0], 0.f);
            h2[t] = pk2(h0, h1);
        }

        // ---- pass B: attn + xi per channel pair, softmax over lanes, fo ----
#pragma unroll 1
        for (int cp = 0; cp < 32; cp++) {
            const int c0 = 2 * cp;

            const ulonglong2* w0 = (const ulonglong2*)(cW + c0 * CINP_);
            u64 A0 = 0, A1 = 0, B0 = 0, B1 = 0;
#pragma unroll
            for (int q = 0; q < 17; q++) {
                ulonglong2 u = w0[q];
                ulonglong2 v = w0[q + 17];
                fma2(A0, u.x, x2[2 * q]);
                fma2(A1, u.y, x2[2 * q + 1]);
                fma2(B0, v.x, x2[2 * q]);
                fma2(B1, v.y, x2[2 * q + 1]);
            }
            const float at0 = red2(A0, A1) + cW[12800 + c0];
            const float at1 = red2(B0, B1) + cW[12801 + c0];

            const ulonglong2* v0 = (const ulonglong2*)(cW + 8704 + c0 * 64);
            u64 P0 = 0, P1 = 0, Q0 = 0, Q1 = 0;
#pragma unroll
            for (int q = 0; q < 16; q++) {
                ulonglong2 u = v0[q];
                ulonglong2 v = v0[q + 16];
                fma2(P0, u.x, h2[2 * q]);
                fma2(P1, u.y, h2[2 * q + 1]);
                fma2(Q0, v.x, h2[2 * q]);
                fma2(Q1, v.y, h2[2 * q + 1]);
            }
            const float xi0 = red2(P0, P1) + cW[12928 + c0];
            const float xi1 = red2(Q0, Q1) + cW[12929 + c0];

            // softmax over the 32 lanes (neighbors), two channels interleaved
            float m0 = at0, m1 = at1;
#pragma unroll
            for (int o = 16; o > 0; o >>= 1) {
                m0 = fmaxf(m0, __shfl_xor_sync(0xffffffffu, m0, o));
                m1 = fmaxf(m1, __shfl_xor_sync(0xffffffffu, m1, o));
            }
            const float e0 = __expf(at0 - m0);
            const float e1 = __expf(at1 - m1);
            float s0 = e0, t0 = e0 * xi0;
            float s1 = e1, t1 = e1 * xi1;
#pragma unroll
            for (int o = 16; o > 0; o >>= 1) {
                s0 += __shfl_xor_sync(0xffffffffu, s0, o);
                t0 += __shfl_xor_sync(0xffffffffu, t0, o);
                s1 += __shfl_xor_sync(0xffffffffu, s1, o);
                t1 += __shfl_xor_sync(0xffffffffu, t1, o);
            }
            if (lane == 0) {
                float fo0 = fmaxf(__fdividef(t0, s0) + fres[warp * CINP_ + c0], 0.f);
                float fo1 = fmaxf(__fdividef(t1, s1) + fres[warp * CINP_ + c0 + 1], 0.f);
                fo_sh[warp * CINP_ + c0]     = fo0;
                fo_sh[warp * CINP_ + c0 + 1] = fo1;
            }
        }
        __syncwarp();

        // ---- epilogue: FFN (each lane owns channels 2*lane, 2*lane+1) ----
        {
            const int ca = 2 * lane, cb = 2 * lane + 1;
            float g1a = bsf[ca], g1b = bsf[cb];
#pragma unroll
            for (int i = 0; i < 64; i++) {
                float  fv = fo_sh[warp * CINP_ + i];
                float2 w  = ((const float2*)(Wf1T + i * 64))[lane];
                g1a += w.x * fv;
                g1b += w.y * fv;
            }
            g1a = fmaxf(g1a, 0.f);
            g1b = fmaxf(g1b, 0.f);
            ((float2*)(g1_sh + warp * CINP_))[lane] = make_float2(g1a, g1b);
            __syncwarp();

            float g2a = bsf[64 + ca], g2b = bsf[64 + cb];
#pragma unroll
            for (int i = 0; i < 64; i++) {
                float  gv = g1_sh[warp * CINP_ + i];
                float2 w  = ((const float2*)(Wf2T + i * 64))[lane];
                g2a += w.x * gv;
                g2b += w.y * gv;
            }
            const float f2a = fmaxf(g2a + fo_sh[warp * CINP_ + ca], 0.f);
            const float f2b = fmaxf(g2b + fo_sh[warp * CINP_ + cb], 0.f);
            tile[ca * 33 + nl] = f2a;
            tile[cb * 33 + nl] = f2b;
        }
        __syncwarp();
    }

    // ---- coalesced write of the 32-point tile: f2 [B][C][N] ----
    __syncthreads();
#pragma unroll
    for (int r = warp; r < 64; r += 8)
        out_f2[((size_t)b * 64 + r) * N_ + n0 + lane] = tile[r * 33 + lane];
}

// ---------------------------------------------------------------------------
// launch
// ---------------------------------------------------------------------------
extern "C" void kernel_launch(void* const* d_in, const int* in_sizes, int n_in,
                              void* d_out, int out_size)
{
    const float* p      = (const float*)d_in[0];
    const float* f      = (const float*)d_in[1];
    const int*   idx    = (const int*)d_in[2];
    const float* W_attn = (const float*)d_in[3];
    const float* b_attn = (const float*)d_in[4];
    const float* W1     = (const float*)d_in[5];
    const float* b1     = (const float*)d_in[6];
    const float* W2     = (const float*)d_in[7];
    const float* b2     = (const float*)d_in[8];
    const float* Wf1    = (const float*)d_in[9];
    const float* bf1    = (const float*)d_in[10];
    const float* Wf2    = (const float*)d_in[11];
    const float* bf2    = (const float*)d_in[12];

    float* out = (float*)d_out;
    const int psz = B_ * N_ * 3;
    const int fsz = B_ * C_ * N_;

    float* out_f2 = out;
    if (out_size >= psz + fsz) {
        cudaMemcpyAsync(out, p, (size_t)psz * sizeof(float),
                        cudaMemcpyDeviceToDevice);
        out_f2 = out + psz;
    }

    // stage + reorder weights, then copy into constant memory
    stage_weights_kernel<<<16, 256>>>(W_attn, W1, W2, b_attn, b1, b2);
    void* stage_ptr = nullptr;
    cudaGetSymbolAddress(&stage_ptr, g_stage);
    cudaMemcpyToSymbolAsync(cW, stage_ptr, CW_FLOATS * sizeof(float), 0,
                            cudaMemcpyDeviceToDevice, 0);

    transpose_f_kernel<<<dim3(N_ / 32, C_ / 32, B_), dim3(32, 8)>>>(f);

    lpamlp_kernel<<<dim3(N_ / 32, B_), 256>>>(
        p, idx, Wf1, bf1, Wf2, bf2, out_f2);
}

// round 4
// speedup vs baseline: 1.7448x; 1.5342x over previous
#include <cuda_runtime.h>
#include <cstdint>
#include <cstddef>

#define B_ 4
#define N_ 8192
#define K_ 32
#define C_ 64

#define RS 288   // attn/h row stride in floats (8 pts * 36)
#define PS 36    // per-point column-slot stride in floats

// precomputed linear parts: Ga = Wa_f @ f + b_attn, G1 = W1_f @ f + b1,
// stored [b][n][c] (256B contiguous per point for cheap gathers)
__device__ float g_Ga[(size_t)B_ * N_ * C_];
__device__ float g_G1[(size_t)B_ * N_ * C_];

// ---------------------------------------------------------------------------
// precompute kernel: 64 points per block, 256 threads (64 n x 4 c-groups)
// ---------------------------------------------------------------------------
__global__ void __launch_bounds__(256) precompute_kernel(
    const float* __restrict__ f,
    const float* __restrict__ Wa, const float* __restrict__ ba,
    const float* __restrict__ W1, const float* __restrict__ b1)
{
    __shared__ float4 Wa4[1024];   // [c][16] float4 of W_attn cols 3..66
    __shared__ float4 W14[1024];
    __shared__ float bsa[64], bs1[64];
    const int tid = threadIdx.x;
    const int b = blockIdx.y, n0 = blockIdx.x * 64;

    for (int i = tid; i < 1024; i += 256) {
        int c = i >> 4, j = (i & 15) * 4;
        Wa4[i] = make_float4(Wa[c*67+3+j], Wa[c*67+4+j], Wa[c*67+5+j], Wa[c*67+6+j]);
        W14[i] = make_float4(W1[c*67+3+j], W1[c*67+4+j], W1[c*67+5+j], W1[c*67+6+j]);
    }
    if (tid < 64) { bsa[tid] = ba[tid]; bs1[tid] = b1[tid]; }
    __syncthreads();

    const int nl = tid & 63, c0 = (tid >> 6) * 16;
    const int n = n0 + nl;
    float x[64];
#pragma unroll
    for (int i = 0; i < 64; i++) x[i] = f[((size_t)b * 64 + i) * N_ + n];

    float oA[16], oB[16];
#pragma unroll
    for (int cc = 0; cc < 16; cc++) {
        const int c = c0 + cc;
        float accA = bsa[c], accB = bs1[c];
#pragma unroll
        for (int q = 0; q < 16; q++) {
            float4 w = Wa4[c * 16 + q];
            float4 v = W14[c * 16 + q];
            accA += w.x*x[4*q] + w.y*x[4*q+1] + w.z*x[4*q+2] + w.w*x[4*q+3];
            accB += v.x*x[4*q] + v.y*x[4*q+1] + v.z*x[4*q+2] + v.w*x[4*q+3];
        }
        oA[cc] = accA; oB[cc] = accB;
    }
    float4* dstA = (float4*)(g_Ga + ((size_t)b * N_ + n) * 64 + c0);
    float4* dstB = (float4*)(g_G1 + ((size_t)b * N_ + n) * 64 + c0);
#pragma unroll
    for (int q = 0; q < 4; q++) {
        dstA[q] = make_float4(oA[4*q], oA[4*q+1], oA[4*q+2], oA[4*q+3]);
        dstB[q] = make_float4(oB[4*q], oB[4*q+1], oB[4*q+2], oB[4*q+3]);
    }
}

// ---------------------------------------------------------------------------
// main kernel: 8 points / block, 256 threads
//   G: gather Ga/G1[nb] + dp linear -> attn, h in smem (padded layout)
//   S: per-(c,pt) softmax over 32 neighbors (in-place -> ca)
//   M: register-tiled GEMM xi = W2 @ h folded with ca weighting -> fo
//   F: FFN per point (warp = point), residuals, output
// ---------------------------------------------------------------------------
__global__ void __launch_bounds__(256, 1) lpamlp_main_kernel(
    const float* __restrict__ p, const int* __restrict__ idx,
    const float* __restrict__ f,
    const float* __restrict__ Wa, const float* __restrict__ W1,
    const float* __restrict__ W2, const float* __restrict__ b2,
    const float* __restrict__ Wf1, const float* __restrict__ bf1,
    const float* __restrict__ Wf2, const float* __restrict__ bf2,
    float* __restrict__ out_f2)
{
    extern __shared__ float sm[];
    float*  attn  = sm;                    // 64*288
    float*  hbuf  = attn + 64 * RS;        // 64*288
    float*  W2T   = hbuf + 64 * RS;        // [k][c] 4096
    float*  Wf1T  = W2T + 4096;            // [i][o] 4096
    float*  Wf2T  = Wf1T + 4096;           // [i][o] 4096
    float4* Wap4  = (float4*)(Wf2T + 4096); // 64
    float4* W1p4  = Wap4 + 64;              // 64
    float*  bias  = (float*)(W1p4 + 64);    // b2 | bf1 | bf2
    float*  fo_sh = bias + 192;             // 8*64
    float*  g1_sh = fo_sh + 512;            // 8*64

    const int tid = threadIdx.x;
    const int b = blockIdx.y, n0 = blockIdx.x * 8;
    const int wp = tid >> 5, lane = tid & 31;

    // ---- init: weights into smem ----
    for (int i = tid; i < 4096; i += 256) {
        W2T[(i & 63) * 64 + (i >> 6)] = W2[i];
        int r = i >> 6, c = i & 63;
        Wf1T[c * 64 + r] = Wf1[i];
        Wf2T[c * 64 + r] = Wf2[i];
    }
    if (tid < 64) {
        Wap4[tid] = make_float4(Wa[tid*67], Wa[tid*67+1], Wa[tid*67+2], 0.f);
        W1p4[tid] = make_float4(W1[tid*67], W1[tid*67+1], W1[tid*67+2], 0.f);
        bias[tid]       = b2[tid];
        bias[64 + tid]  = bf1[tid];
        bias[128 + tid] = bf2[tid];
    }
    __syncthreads();

    // ---- phase G: column = (pt=warp, k=lane) ----
    {
        const int n = n0 + wp;
        const int nb = idx[((size_t)b * N_ + n) * K_ + lane];
        const float* pj = p + ((size_t)b * N_ + nb) * 3;
        const float* pc = p + ((size_t)b * N_ + n) * 3;
        const float d0 = pj[0] - pc[0], d1 = pj[1] - pc[1], d2 = pj[2] - pc[2];
        const float4* gaR = (const float4*)(g_Ga + ((size_t)b * N_ + nb) * 64);
        const float4* g1R = (const float4*)(g_G1 + ((size_t)b * N_ + nb) * 64);
        const int off = wp * PS + lane;
#pragma unroll
        for (int c4 = 0; c4 < 16; c4++) {
            float4 ga = gaR[c4], gh = g1R[c4];
            float gav[4] = {ga.x, ga.y, ga.z, ga.w};
            float ghv[4] = {gh.x, gh.y, gh.z, gh.w};
#pragma unroll
            for (int j = 0; j < 4; j++) {
                const int c = c4 * 4 + j;
                float4 wa = Wap4[c], w1 = W1p4[c];
                attn[c * RS + off] = gav[j] + wa.x*d0 + wa.y*d1 + wa.z*d2;
                hbuf[c * RS + off] = fmaxf(ghv[j] + w1.x*d0 + w1.y*d1 + w1.z*d2, 0.f);
            }
        }
    }
    __syncthreads();

    // ---- phase S: softmax over neighbors, items (c, pt), 2 per thread ----
#pragma unroll
    for (int it = 0; it < 2; it++) {
        const int item = tid + it * 256;
        const int c = item >> 3, pt2 = item & 7;
        float4* row = (float4*)(attn + c * RS + pt2 * PS);
        float4 v[8];
#pragma unroll
        for (int q = 0; q < 8; q++) v[q] = row[q];
        float m = -1e30f;
#pragma unroll
        for (int q = 0; q < 8; q++)
            m = fmaxf(m, fmaxf(fmaxf(v[q].x, v[q].y), fmaxf(v[q].z, v[q].w)));
        float s = 0.f;
#pragma unroll
        for (int q = 0; q < 8; q++) {
            v[q].x = __expf(v[q].x - m); v[q].y = __expf(v[q].y - m);
            v[q].z = __expf(v[q].z - m); v[q].w = __expf(v[q].w - m);
            s += (v[q].x + v[q].y) + (v[q].z + v[q].w);
        }
        const float inv = __fdividef(1.f, s);
#pragma unroll
        for (int q = 0; q < 8; q++) {
            v[q].x *= inv; v[q].y *= inv; v[q].z *= inv; v[q].w *= inv;
            row[q] = v[q];
        }
    }
    __syncthreads();

    // ---- phase M: xi = W2 @ h register-tiled, ca-weighted epilogue ----
    {
        const int c0 = wp * 8;
        const int pt3 = lane >> 2, q = lane & 3;
        const int colbase = pt3 * PS + q * 8;
        float acc[8][8];
#pragma unroll
        for (int a = 0; a < 8; a++)
#pragma unroll
            for (int j = 0; j < 8; j++) acc[a][j] = 0.f;

#pragma unroll 4
        for (int k = 0; k < 64; k++) {
            float4 a0 = *(float4*)(W2T + k * 64 + c0);
            float4 a1 = *(float4*)(W2T + k * 64 + c0 + 4);
            float4 b0 = *(float4*)(hbuf + k * RS + colbase);
            float4 b1 = *(float4*)(hbuf + k * RS + colbase + 4);
            float av[8] = {a0.x, a0.y, a0.z, a0.w, a1.x, a1.y, a1.z, a1.w};
            float bv[8] = {b0.x, b0.y, b0.z, b0.w, b1.x, b1.y, b1.z, b1.w};
#pragma unroll
            for (int a = 0; a < 8; a++)
#pragma unroll
                for (int j = 0; j < 8; j++) acc[a][j] += av[a] * bv[j];
        }

#pragma unroll
        for (int a = 0; a < 8; a++) {
            const int c = c0 + a;
            float4 u0 = *(float4*)(attn + c * RS + colbase);
            float4 u1 = *(float4*)(attn + c * RS + colbase + 4);
            float part = u0.x*acc[a][0] + u0.y*acc[a][1] + u0.z*acc[a][2] + u0.w*acc[a][3]
                       + u1.x*acc[a][4] + u1.y*acc[a][5] + u1.z*acc[a][6] + u1.w*acc[a][7];
            part += __shfl_xor_sync(0xffffffffu, part, 1);
            part += __shfl_xor_sync(0xffffffffu, part, 2);
            if (q == 0) {
                const float fr = f[((size_t)b * 64 + c) * N_ + n0 + pt3];
                fo_sh[pt3 * 64 + c] = fmaxf(part + bias[c] + fr, 0.f);
            }
        }
    }
    __syncthreads();

    // ---- phase F: FFN per point (warp = point) ----
    {
        const int n = n0 + wp;
        const int ca = 2 * lane, cb = ca + 1;
        float g1a = bias[64 + ca], g1b = bias[64 + cb];
#pragma unroll
        for (int i = 0; i < 64; i++) {
            const float fv = fo_sh[wp * 64 + i];
            const float2 wv = ((const float2*)(Wf1T + i * 64))[lane];
            g1a += wv.x * fv;
            g1b += wv.y * fv;
        }
        g1a = fmaxf(g1a, 0.f);
        g1b = fmaxf(g1b, 0.f);
        ((float2*)(g1_sh + wp * 64))[lane] = make_float2(g1a, g1b);
        __syncwarp();

        float g2a = bias[128 + ca], g2b = bias[128 + cb];
#pragma unroll
        for (int i = 0; i < 64; i++) {
            const float gv = g1_sh[wp * 64 + i];
            const float2 wv = ((const float2*)(Wf2T + i * 64))[lane];
            g2a += wv.x * gv;
            g2b += wv.y * gv;
        }
        out_f2[((size_t)b * 64 + ca) * N_ + n] = fmaxf(g2a + fo_sh[wp * 64 + ca], 0.f);
        out_f2[((size_t)b * 64 + cb) * N_ + n] = fmaxf(g2b + fo_sh[wp * 64 + cb], 0.f);
    }
}

// ---------------------------------------------------------------------------
// launch
// ---------------------------------------------------------------------------
static const int SMEM_FLOATS = 64*RS + 64*RS + 4096 + 4096 + 4096
                             + 256 + 256 + 192 + 512 + 512;
static const int SMEM_BYTES = SMEM_FLOATS * 4;   // 203,520 B

extern "C" void kernel_launch(void* const* d_in, const int* in_sizes, int n_in,
                              void* d_out, int out_size)
{
    const float* p      = (const float*)d_in[0];
    const float* f      = (const float*)d_in[1];
    const int*   idx    = (const int*)d_in[2];
    const float* W_attn = (const float*)d_in[3];
    const float* b_attn = (const float*)d_in[4];
    const float* W1     = (const float*)d_in[5];
    const float* b1     = (const float*)d_in[6];
    const float* W2     = (const float*)d_in[7];
    const float* b2     = (const float*)d_in[8];
    const float* Wf1    = (const float*)d_in[9];
    const float* bf1    = (const float*)d_in[10];
    const float* Wf2    = (const float*)d_in[11];
    const float* bf2    = (const float*)d_in[12];

    float* out = (float*)d_out;
    const int psz = B_ * N_ * 3;
    const int fsz = B_ * C_ * N_;

    float* out_f2 = out;
    if (out_size >= psz + fsz) {
        cudaMemcpyAsync(out, p, (size_t)psz * sizeof(float),
                        cudaMemcpyDeviceToDevice);
        out_f2 = out + psz;
    }

    precompute_kernel<<<dim3(N_ / 64, B_), 256>>>(f, W_attn, b_attn, W1, b1);

    cudaFuncSetAttribute(lpamlp_main_kernel,
                         cudaFuncAttributeMaxDynamicSharedMemorySize, SMEM_BYTES);
    lpamlp_main_kernel<<<dim3(N_ / 8, B_), 256, SMEM_BYTES>>>(
        p, idx, f, W_attn, W1, W2, b2, Wf1, bf1, Wf2, bf2, out_f2);
}